// round 9
// baseline (speedup 1.0000x reference)
#include <cuda_runtime.h>
#include <cuda_bf16.h>

#define T_BINS 16384
#define EDGE   4
#define WIN    9      // 2*EDGE+1
#define D_DIM  128    // 32 float4 per row

// One warp per batch element. Lane l owns output floats [4l, 4l+4).
// Lanes 0..8 each compute one softmax term; weights broadcast via shfl.
__global__ void __launch_bounds__(256, 8)
hwnet_kernel(const float* __restrict__ xin,
             const float* __restrict__ et,
             const float* __restrict__ emin,
             const float* __restrict__ emax,
             const float* __restrict__ vt,
             float* __restrict__ out,
             int B)
{
    int warp = (int)((blockIdx.x * blockDim.x + threadIdx.x) >> 5);
    int lane = threadIdx.x & 31;
    if (warp >= B) return;

    float x = __ldg(&xin[warp]);

    // Bins are uniform (edges = i * 2^-14, exact in fp32), so the floor guess
    // is exact; fixups kept for robustness against table perturbations.
    int i = (int)(x * (float)T_BINS);
    i = min(max(i, 0), T_BINS - 1);
    while (i > 0 && x < __ldg(&emin[i])) --i;
    while (i < T_BINS - 1 && x > __ldg(&emax[i])) ++i;
    // argmax-first semantics: if x sits exactly on the shared edge, the
    // reference's argmax picks the LOWER bin (x <= emax[i-1] means x == emin[i]).
    if (i > 0 && x <= __ldg(&emax[i - 1])) --i;

    int ic = min(max(i, EDGE), T_BINS - 1 - EDGE);

    float lo   = __ldg(&emin[i]);
    float hi   = __ldg(&emax[i]);
    float ctr  = __ldg(&et[i]);
    float d0   = (x - ctr) / (hi - lo);
    float base = d0 - (float)(ic - i);

    // Softmax numerator: one exp per lane for lanes 0..8 only (saves 32x MUFU).
    // No max-subtraction needed: terms are exp(-10 d^2) <= 1, and the nearest
    // bin guarantees the max term >= exp(-2.5); far terms underflow to 0.
    float e = 0.0f;
    if (lane < WIN) {
        float d = base - (float)(lane - EDGE);
        e = __expf(-10.0f * d * d);
    }
    float s = e;
    #pragma unroll
    for (int off = 16; off > 0; off >>= 1)
        s += __shfl_xor_sync(0xffffffffu, s, off);
    float inv = 1.0f / s;

    const float4* vt4 = (const float4*)vt;
    size_t row0 = (size_t)(ic - EDGE) * 32 + (size_t)lane;

    float4 acc = make_float4(0.f, 0.f, 0.f, 0.f);
    #pragma unroll
    for (int w = 0; w < WIN; ++w) {
        float wt = __shfl_sync(0xffffffffu, e, w) * inv;
        float4 v = __ldg(&vt4[row0 + (size_t)w * 32]);
        acc.x = fmaf(v.x, wt, acc.x);
        acc.y = fmaf(v.y, wt, acc.y);
        acc.z = fmaf(v.z, wt, acc.z);
        acc.w = fmaf(v.w, wt, acc.w);
    }
    ((float4*)out)[(size_t)warp * 32 + lane] = acc;
}

extern "C" void kernel_launch(void* const* d_in, const int* in_sizes, int n_in,
                              void* d_out, int out_size)
{
    // metadata order: inputs [B,1], evaluate_table [T,1], evaluate_min_table [T,1],
    //                 evaluate_max_table [T,1], vector_table [T,D]
    const float* xin  = (const float*)d_in[0];
    const float* et   = (const float*)d_in[1];
    const float* emin = (const float*)d_in[2];
    const float* emax = (const float*)d_in[3];
    const float* vt   = (const float*)d_in[4];
    float* out = (float*)d_out;

    int B = in_sizes[0];                 // 8192
    int threads = 256;                   // 8 warps/block, 1 sample per warp
    int blocks  = (B * 32 + threads - 1) / threads;

    hwnet_kernel<<<blocks, threads>>>(xin, et, emin, emax, vt, out, B);
}